// round 2
// baseline (speedup 1.0000x reference)
#include <cuda_runtime.h>
#include <cuda_bf16.h>
#include <mma.h>

using namespace nvcuda;

// Problem constants
#define BATCH 4
#define CC    256      // channels
#define NN    4096     // H*W
#define DKK   32       // f/g projection dim

// ---------------------------------------------------------------------------
// Scratch (static device globals — allocation-free per harness rules)
// ---------------------------------------------------------------------------
__device__ __nv_bfloat16 g_fK[(size_t)BATCH * DKK * NN];        // f  [b][d][n]   1 MB
__device__ __nv_bfloat16 g_gT[(size_t)BATCH * NN * DKK];        // gT [b][n][d]   1 MB
__device__ float         g_hh[(size_t)BATCH * CC * NN];         // hh [b][c][n]  16 MB
__device__ __nv_bfloat16 g_hb[(size_t)BATCH * CC * NN];         // hh/Z bf16      8 MB
__device__ float         g_Z [(size_t)BATCH * NN];              // row sums      64 KB
__device__ __nv_bfloat16 g_E [(size_t)BATCH * NN * NN];         // exp(s)       128 MB

// ---------------------------------------------------------------------------
// Kernel 1: projections (1x1 convs).  out = W @ x + bias, per batch.
// mode 0: f -> g_fK bf16 [d][n]; mode 1: g -> g_gT bf16 [n][d] (transposed);
// mode 2: hh -> g_hh fp32 [c][n].
// Tile: BM=32, BN=128, BK=16, 128 threads (4 warps, each 32x32).
// ---------------------------------------------------------------------------
__global__ void proj_kernel(const float* __restrict__ x,
                            const float* __restrict__ W,
                            const float* __restrict__ bias,
                            int mode)
{
    __shared__ __nv_bfloat16 As[32][16];
    __shared__ __nv_bfloat16 Bs[16][128];
    __shared__ float         Cs[32][128];

    const int b   = blockIdx.z;
    const int m0  = blockIdx.y * 32;
    const int n0  = blockIdx.x * 128;
    const int tid = threadIdx.x;
    const int warp = tid >> 5;          // 0..3, column group

    wmma::fragment<wmma::accumulator, 16, 16, 16, float> acc[2][2];
#pragma unroll
    for (int i = 0; i < 2; i++)
#pragma unroll
        for (int j = 0; j < 2; j++)
            wmma::fill_fragment(acc[i][j], 0.0f);

    const float* xb = x + (size_t)b * CC * NN;

    for (int k0 = 0; k0 < CC; k0 += 16) {
        // A tile: 32x16 from W (fp32 -> bf16)
        for (int idx = tid; idx < 32 * 16; idx += 128) {
            int r = idx >> 4, c = idx & 15;
            As[r][c] = __float2bfloat16(W[(size_t)(m0 + r) * CC + k0 + c]);
        }
        // B tile: 16x128 from x (fp32 -> bf16)
        for (int idx = tid; idx < 16 * 128; idx += 128) {
            int r = idx >> 7, c = idx & 127;
            Bs[r][c] = __float2bfloat16(xb[(size_t)(k0 + r) * NN + n0 + c]);
        }
        __syncthreads();

        wmma::fragment<wmma::matrix_a, 16, 16, 16, __nv_bfloat16, wmma::row_major> af[2];
        wmma::fragment<wmma::matrix_b, 16, 16, 16, __nv_bfloat16, wmma::row_major> bfrag[2];
#pragma unroll
        for (int i = 0; i < 2; i++)
            wmma::load_matrix_sync(af[i], &As[i * 16][0], 16);
#pragma unroll
        for (int j = 0; j < 2; j++)
            wmma::load_matrix_sync(bfrag[j], &Bs[0][warp * 32 + j * 16], 128);
#pragma unroll
        for (int i = 0; i < 2; i++)
#pragma unroll
            for (int j = 0; j < 2; j++)
                wmma::mma_sync(acc[i][j], af[i], bfrag[j], acc[i][j]);
        __syncthreads();
    }

#pragma unroll
    for (int i = 0; i < 2; i++)
#pragma unroll
        for (int j = 0; j < 2; j++)
            wmma::store_matrix_sync(&Cs[i * 16][warp * 32 + j * 16], acc[i][j],
                                    128, wmma::mem_row_major);
    __syncthreads();

    for (int idx = tid; idx < 32 * 128; idx += 128) {
        int r = idx >> 7, c = idx & 127;
        float v = Cs[r][c] + bias[m0 + r];
        if (mode == 0) {
            g_fK[((size_t)b * DKK + (m0 + r)) * NN + n0 + c] = __float2bfloat16(v);
        } else if (mode == 1) {
            g_gT[((size_t)b * NN + (n0 + c)) * DKK + (m0 + r)] = __float2bfloat16(v);
        } else {
            g_hh[((size_t)b * CC + (m0 + r)) * NN + n0 + c] = v;
        }
    }
}

// ---------------------------------------------------------------------------
// Kernel 2: s = gT @ f (M=N=4096, K=32), then E = exp(s) -> bf16 scratch.
// Tile 64x64, 128 threads (4 warps, 2x2, each 32x32).
// ---------------------------------------------------------------------------
__global__ void attn_s_kernel()
{
    __shared__ __nv_bfloat16 As[64][32];   // gT tile [j][d]
    __shared__ __nv_bfloat16 Bs[32][64];   // f  tile [d][i]
    __shared__ float         Cs[64][64];

    const int b   = blockIdx.z;
    const int j0  = blockIdx.y * 64;
    const int i0  = blockIdx.x * 64;
    const int tid = threadIdx.x;
    const int warp = tid >> 5;
    const int wr = warp >> 1, wc = warp & 1;

    // Load A tile: 64 rows x 32 bf16 — contiguous block of g_gT
    {
        const uint4* gA = (const uint4*)(g_gT + ((size_t)b * NN + j0) * DKK);
        uint4* sA = (uint4*)&As[0][0];
        sA[tid]       = gA[tid];
        sA[tid + 128] = gA[tid + 128];
    }
    // Load B tile: 32 rows x 64 bf16 from g_fK rows
    {
        uint4* sB = (uint4*)&Bs[0][0];
#pragma unroll
        for (int p = 0; p < 2; p++) {
            int idx = tid + p * 128;
            int r = idx >> 3, q = idx & 7;
            sB[idx] = *(const uint4*)(g_fK + ((size_t)b * DKK + r) * NN + i0 + q * 8);
        }
    }
    __syncthreads();

    wmma::fragment<wmma::accumulator, 16, 16, 16, float> acc[2][2];
#pragma unroll
    for (int i = 0; i < 2; i++)
#pragma unroll
        for (int j = 0; j < 2; j++)
            wmma::fill_fragment(acc[i][j], 0.0f);

#pragma unroll
    for (int ks = 0; ks < 32; ks += 16) {
        wmma::fragment<wmma::matrix_a, 16, 16, 16, __nv_bfloat16, wmma::row_major> af[2];
        wmma::fragment<wmma::matrix_b, 16, 16, 16, __nv_bfloat16, wmma::row_major> bfrag[2];
#pragma unroll
        for (int i = 0; i < 2; i++)
            wmma::load_matrix_sync(af[i], &As[wr * 32 + i * 16][ks], 32);
#pragma unroll
        for (int j = 0; j < 2; j++)
            wmma::load_matrix_sync(bfrag[j], &Bs[ks][wc * 32 + j * 16], 64);
#pragma unroll
        for (int i = 0; i < 2; i++)
#pragma unroll
            for (int j = 0; j < 2; j++)
                wmma::mma_sync(acc[i][j], af[i], bfrag[j], acc[i][j]);
    }

#pragma unroll
    for (int i = 0; i < 2; i++)
#pragma unroll
        for (int j = 0; j < 2; j++)
            wmma::store_matrix_sync(&Cs[wr * 32 + i * 16][wc * 32 + j * 16],
                                    acc[i][j], 64, wmma::mem_row_major);
    __syncthreads();

    __nv_bfloat16* Eb = g_E + (size_t)b * NN * NN + (size_t)j0 * NN + i0;
    for (int idx = tid; idx < 64 * 64; idx += 128) {
        int r = idx >> 6, c = idx & 63;
        float e = __expf(Cs[r][c]);
        Eb[(size_t)r * NN + c] = __float2bfloat16(e);
    }
}

// ---------------------------------------------------------------------------
// Kernel 2b: deterministic row sums Z[b][j] = sum_i E[b][j][i].
// One warp per row; fixed reduction order (no float atomics).
// ---------------------------------------------------------------------------
__global__ void rowsum_kernel()
{
    const int row  = blockIdx.x * 8 + (threadIdx.x >> 5);  // global row in [0, B*NN)
    const int lane = threadIdx.x & 31;
    const uint4* Er = (const uint4*)(g_E + (size_t)row * NN);

    float s = 0.0f;
    for (int q = lane; q < NN / 8; q += 32) {
        uint4 v = Er[q];
        const __nv_bfloat162* p = (const __nv_bfloat162*)&v;
#pragma unroll
        for (int k = 0; k < 4; k++) {
            float2 f2 = __bfloat1622float2(p[k]);
            s += f2.x + f2.y;
        }
    }
#pragma unroll
    for (int off = 16; off > 0; off >>= 1)
        s += __shfl_down_sync(0xFFFFFFFFu, s, off);
    if (lane == 0) g_Z[row] = s;
}

// ---------------------------------------------------------------------------
// Kernel 3: hb[b][c][j] = bf16( hh[b][c][j] / Z[b][j] )
// ---------------------------------------------------------------------------
__global__ void norm_h_kernel()
{
    size_t idx = (size_t)blockIdx.x * blockDim.x + threadIdx.x;  // < B*C*N = 2^22
    int j = (int)(idx & (NN - 1));
    int b = (int)(idx >> 20);                                    // C*N = 2^20
    g_hb[idx] = __float2bfloat16(g_hh[idx] / g_Z[(size_t)b * NN + j]);
}

// ---------------------------------------------------------------------------
// Kernel 4: out = hb @ E + x   (per batch: [256 x 4096] = [256x4096]·[4096x4096])
// Tile: BM=64, BN=128, BK=32, 256 threads (8 warps 2x4, each 32x32).
// ---------------------------------------------------------------------------
__global__ void out_gemm_kernel(const float* __restrict__ x,
                                float* __restrict__ out)
{
    __shared__ __nv_bfloat16 As[64][32];
    __shared__ __nv_bfloat16 Bs[32][128];

    const int b   = blockIdx.z;
    const int m0  = blockIdx.y * 64;
    const int n0  = blockIdx.x * 128;
    const int tid = threadIdx.x;
    const int warp = tid >> 5;           // 0..7
    const int wr = warp >> 2, wc = warp & 3;

    const __nv_bfloat16* Ab = g_hb + (size_t)b * CC * NN;
    const __nv_bfloat16* Bb = g_E  + (size_t)b * NN * NN;

    wmma::fragment<wmma::accumulator, 16, 16, 16, float> acc[2][2];
#pragma unroll
    for (int i = 0; i < 2; i++)
#pragma unroll
        for (int j = 0; j < 2; j++)
            wmma::fill_fragment(acc[i][j], 0.0f);

    for (int k0 = 0; k0 < NN; k0 += 32) {
        // A tile: 64x32 bf16 = 256 uint4, one per thread
        {
            int r = tid >> 2, q = tid & 3;
            ((uint4*)As)[tid] = *(const uint4*)(Ab + (size_t)(m0 + r) * NN + k0 + q * 8);
        }
        // B tile: 32x128 bf16 = 512 uint4, two per thread
#pragma unroll
        for (int p = 0; p < 2; p++) {
            int idx = tid + p * 256;
            int r = idx >> 4, q = idx & 15;
            ((uint4*)Bs)[idx] = *(const uint4*)(Bb + (size_t)(k0 + r) * NN + n0 + q * 8);
        }
        __syncthreads();

#pragma unroll
        for (int ks = 0; ks < 32; ks += 16) {
            wmma::fragment<wmma::matrix_a, 16, 16, 16, __nv_bfloat16, wmma::row_major> af[2];
            wmma::fragment<wmma::matrix_b, 16, 16, 16, __nv_bfloat16, wmma::row_major> bfrag[2];
#pragma unroll
            for (int i = 0; i < 2; i++)
                wmma::load_matrix_sync(af[i], &As[wr * 32 + i * 16][ks], 32);
#pragma unroll
            for (int j = 0; j < 2; j++)
                wmma::load_matrix_sync(bfrag[j], &Bs[ks][wc * 32 + j * 16], 128);
#pragma unroll
            for (int i = 0; i < 2; i++)
#pragma unroll
                for (int j = 0; j < 2; j++)
                    wmma::mma_sync(acc[i][j], af[i], bfrag[j], acc[i][j]);
        }
        __syncthreads();
    }

    // Epilogue: out = acc + x (residual), fragment-wise
    const float* xb = x   + (size_t)b * CC * NN;
    float*       ob = out + (size_t)b * CC * NN;
#pragma unroll
    for (int i = 0; i < 2; i++) {
#pragma unroll
        for (int j = 0; j < 2; j++) {
            int row = m0 + wr * 32 + i * 16;
            int col = n0 + wc * 32 + j * 16;
            wmma::fragment<wmma::accumulator, 16, 16, 16, float> xf;
            wmma::load_matrix_sync(xf, xb + (size_t)row * NN + col, NN, wmma::mem_row_major);
#pragma unroll
            for (int e = 0; e < xf.num_elements; e++)
                acc[i][j].x[e] += xf.x[e];
            wmma::store_matrix_sync(ob + (size_t)row * NN + col, acc[i][j], NN,
                                    wmma::mem_row_major);
        }
    }
}

// ---------------------------------------------------------------------------
// Launch (graph-capturable: kernel launches only, stream-ordered deps)
// ---------------------------------------------------------------------------
extern "C" void kernel_launch(void* const* d_in, const int* in_sizes, int n_in,
                              void* d_out, int out_size)
{
    const float* x  = (const float*)d_in[0];
    const float* Wf = (const float*)d_in[1];
    const float* bf = (const float*)d_in[2];
    const float* Wg = (const float*)d_in[3];
    const float* bg = (const float*)d_in[4];
    const float* Wh = (const float*)d_in[5];
    const float* bh = (const float*)d_in[6];
    float* out = (float*)d_out;

    // Projections: f, g (M=32), hh (M=256)
    dim3 gFG(NN / 128, 1, BATCH);
    proj_kernel<<<gFG, 128>>>(x, Wf, bf, 0);
    proj_kernel<<<gFG, 128>>>(x, Wg, bg, 1);
    dim3 gH(NN / 128, CC / 32, BATCH);
    proj_kernel<<<gH, 128>>>(x, Wh, bh, 2);

    // s = gT f ; E = exp(s)
    dim3 gS(NN / 64, NN / 64, BATCH);
    attn_s_kernel<<<gS, 128>>>();

    // Z = row sums of E (deterministic)
    rowsum_kernel<<<(BATCH * NN) / 8, 256>>>();

    // hb = hh / Z (bf16)
    norm_h_kernel<<<(BATCH * CC * NN) / 256, 256>>>();

    // out = hb @ E + x
    dim3 gO(NN / 128, CC / 64, BATCH);
    out_gemm_kernel<<<gO, 256>>>(x, out);
}

// round 6
// speedup vs baseline: 2.1542x; 2.1542x over previous
#include <cuda_runtime.h>
#include <cuda_bf16.h>
#include <mma.h>
#include <cstdint>

using namespace nvcuda;

#define BATCH 4
#define CC    256
#define NN    4096
#define DKK   32

// ---------------------------------------------------------------------------
// Scratch
// ---------------------------------------------------------------------------
__device__ __nv_bfloat16 g_fK[(size_t)BATCH * DKK * NN];   // f  [b][d][n]
__device__ __nv_bfloat16 g_gT[(size_t)BATCH * NN * DKK];   // gT [b][n][d]
__device__ __nv_bfloat16 g_hc[(size_t)BATCH * CC * NN];    // hh [b][c][n] bf16 (unnormalized)
__device__ __nv_bfloat16 g_hb[(size_t)BATCH * CC * NN];    // hh/Z bf16
__device__ float         g_Z [(size_t)BATCH * NN];         // row sums (fp32)
__device__ __nv_bfloat16 g_E [(size_t)BATCH * NN * NN];    // exp(s) bf16

// ---------------------------------------------------------------------------
// PTX helpers
// ---------------------------------------------------------------------------
__device__ __forceinline__ uint32_t smem_u32(const void* p) {
    return (uint32_t)__cvta_generic_to_shared(p);
}
__device__ __forceinline__ void ldsm_x4(uint32_t& r0, uint32_t& r1, uint32_t& r2, uint32_t& r3,
                                        uint32_t addr) {
    asm volatile("ldmatrix.sync.aligned.m8n8.x4.shared.b16 {%0,%1,%2,%3}, [%4];"
                 : "=r"(r0), "=r"(r1), "=r"(r2), "=r"(r3) : "r"(addr));
}
__device__ __forceinline__ void ldsm_x2_t(uint32_t& r0, uint32_t& r1, uint32_t addr) {
    asm volatile("ldmatrix.sync.aligned.m8n8.x2.trans.shared.b16 {%0,%1}, [%2];"
                 : "=r"(r0), "=r"(r1) : "r"(addr));
}
__device__ __forceinline__ void mma_16816(float* d, const uint32_t* a, uint32_t b0, uint32_t b1) {
    asm volatile("mma.sync.aligned.m16n8k16.row.col.f32.bf16.bf16.f32 "
                 "{%0,%1,%2,%3}, {%4,%5,%6,%7}, {%8,%9}, {%0,%1,%2,%3};"
                 : "+f"(d[0]), "+f"(d[1]), "+f"(d[2]), "+f"(d[3])
                 : "r"(a[0]), "r"(a[1]), "r"(a[2]), "r"(a[3]), "r"(b0), "r"(b1));
}
__device__ __forceinline__ void cp_async16(uint32_t dst, const void* src) {
    asm volatile("cp.async.cg.shared.global [%0], [%1], 16;" :: "r"(dst), "l"(src));
}
__device__ __forceinline__ void cp_commit() { asm volatile("cp.async.commit_group;"); }
__device__ __forceinline__ void cp_wait1()  { asm volatile("cp.async.wait_group 1;"); }
__device__ __forceinline__ void cp_wait0()  { asm volatile("cp.async.wait_group 0;"); }

// ---------------------------------------------------------------------------
// Kernel 1: projections. mode 0: f->g_fK [d][n]; mode 1: g->g_gT [n][d];
// mode 2: hh->g_hc bf16 [c][n].
// ---------------------------------------------------------------------------
__global__ void proj_kernel(const float* __restrict__ x,
                            const float* __restrict__ W,
                            const float* __restrict__ bias,
                            int mode)
{
    __shared__ __nv_bfloat16 As[32][16];
    __shared__ __nv_bfloat16 Bs[16][128];
    __shared__ float         Cs[32][128];

    const int b   = blockIdx.z;
    const int m0  = blockIdx.y * 32;
    const int n0  = blockIdx.x * 128;
    const int tid = threadIdx.x;
    const int warp = tid >> 5;

    wmma::fragment<wmma::accumulator, 16, 16, 16, float> acc[2][2];
#pragma unroll
    for (int i = 0; i < 2; i++)
#pragma unroll
        for (int j = 0; j < 2; j++)
            wmma::fill_fragment(acc[i][j], 0.0f);

    const float* xb = x + (size_t)b * CC * NN;

    for (int k0 = 0; k0 < CC; k0 += 16) {
        for (int idx = tid; idx < 32 * 16; idx += 128) {
            int r = idx >> 4, c = idx & 15;
            As[r][c] = __float2bfloat16(W[(size_t)(m0 + r) * CC + k0 + c]);
        }
        for (int idx = tid; idx < 16 * 128; idx += 128) {
            int r = idx >> 7, c = idx & 127;
            Bs[r][c] = __float2bfloat16(xb[(size_t)(k0 + r) * NN + n0 + c]);
        }
        __syncthreads();

        wmma::fragment<wmma::matrix_a, 16, 16, 16, __nv_bfloat16, wmma::row_major> af[2];
        wmma::fragment<wmma::matrix_b, 16, 16, 16, __nv_bfloat16, wmma::row_major> bfr[2];
#pragma unroll
        for (int i = 0; i < 2; i++)
            wmma::load_matrix_sync(af[i], &As[i * 16][0], 16);
#pragma unroll
        for (int j = 0; j < 2; j++)
            wmma::load_matrix_sync(bfr[j], &Bs[0][warp * 32 + j * 16], 128);
#pragma unroll
        for (int i = 0; i < 2; i++)
#pragma unroll
            for (int j = 0; j < 2; j++)
                wmma::mma_sync(acc[i][j], af[i], bfr[j], acc[i][j]);
        __syncthreads();
    }

#pragma unroll
    for (int i = 0; i < 2; i++)
#pragma unroll
        for (int j = 0; j < 2; j++)
            wmma::store_matrix_sync(&Cs[i * 16][warp * 32 + j * 16], acc[i][j],
                                    128, wmma::mem_row_major);
    __syncthreads();

    for (int idx = tid; idx < 32 * 128; idx += 128) {
        int r = idx >> 7, c = idx & 127;
        float v = Cs[r][c] + bias[m0 + r];
        if (mode == 0) {
            g_fK[((size_t)b * DKK + (m0 + r)) * NN + n0 + c] = __float2bfloat16(v);
        } else if (mode == 1) {
            g_gT[((size_t)b * NN + (n0 + c)) * DKK + (m0 + r)] = __float2bfloat16(v);
        } else {
            g_hc[((size_t)b * CC + (m0 + r)) * NN + n0 + c] = __float2bfloat16(v);
        }
    }
}

// ---------------------------------------------------------------------------
// Kernel 2 (fused): per block = 64 j-rows of one batch.
//   loops over all i: s = gT_tile @ f_tile (raw mma), E = exp(s) -> bf16 store,
//   Z_j accumulated in registers (deterministic), written at end.
// 256 threads = 8 warps; warp w: rows (w>>1)*16..+16, cols (w&1)*32..+32.
// ---------------------------------------------------------------------------
__global__ __launch_bounds__(256) void attn_fused_kernel()
{
    __shared__ __nv_bfloat16 Ags[64][40];        // gT tile, padded
    __shared__ __nv_bfloat16 Bfs[2][32][72];     // f tile, double buffered
    __shared__ __nv_bfloat16 Es[2][64][72];      // exp(s) staging
    __shared__ float         Zp[2][64];

    const int b   = blockIdx.y;
    const int j0  = blockIdx.x * 64;
    const int tid = threadIdx.x;
    const int w   = tid >> 5;
    const int l   = tid & 31;
    const int jr  = (w >> 1) * 16;   // warp row base (local)
    const int cw  = (w & 1);         // warp col group (32 cols)

    // ---- load gT tile [64][32] once ----
    {
        int r = tid >> 2, q = tid & 3;
        *(uint4*)&Ags[r][q * 8] =
            *(const uint4*)(g_gT + ((size_t)b * NN + j0 + r) * DKK + q * 8);
    }
    // ---- load f tile for i0=0 ----
    {
        int r = tid >> 3, q = tid & 7;
        *(uint4*)&Bfs[0][r][q * 8] =
            *(const uint4*)(g_fK + ((size_t)b * DKK + r) * NN + q * 8);
    }
    __syncthreads();

    // ---- A fragments, register-resident for whole kernel ----
    uint32_t a[2][4];
#pragma unroll
    for (int kf = 0; kf < 2; kf++) {
        uint32_t addr = smem_u32(&Ags[jr + (l & 15)][kf * 16 + (l >> 4) * 8]);
        ldsm_x4(a[kf][0], a[kf][1], a[kf][2], a[kf][3], addr);
    }

    float zacc0 = 0.0f, zacc1 = 0.0f;   // rows jr+(l>>2), jr+(l>>2)+8
    __nv_bfloat16* Eb = g_E + (size_t)b * NN * NN + (size_t)j0 * NN;

    const int NIT = NN / 64;   // 64
    for (int it = 0; it < NIT; it++) {
        const int cur = it & 1;
        // prefetch next f tile into regs
        uint4 rnext;
        if (it + 1 < NIT) {
            int r = tid >> 3, q = tid & 7;
            rnext = *(const uint4*)(g_fK + ((size_t)b * DKK + r) * NN +
                                    (it + 1) * 64 + q * 8);
        }

        // compute s tile, exp, stage to Es[cur]
#pragma unroll
        for (int nf = 0; nf < 4; nf++) {
            const int cb = cw * 32 + nf * 8;
            float d[4] = {0.f, 0.f, 0.f, 0.f};
            uint32_t b0, b1;
            ldsm_x2_t(b0, b1, smem_u32(&Bfs[cur][l & 15][cb]));
            mma_16816(d, a[0], b0, b1);
            ldsm_x2_t(b0, b1, smem_u32(&Bfs[cur][16 + (l & 15)][cb]));
            mma_16816(d, a[1], b0, b1);

            float e0 = __expf(d[0]), e1 = __expf(d[1]);
            float e2 = __expf(d[2]), e3 = __expf(d[3]);
            zacc0 += e0 + e1;
            zacc1 += e2 + e3;
            int r1 = jr + (l >> 2);
            int col = cb + (l & 3) * 2;
            *(__nv_bfloat162*)&Es[cur][r1][col]     = __floats2bfloat162_rn(e0, e1);
            *(__nv_bfloat162*)&Es[cur][r1 + 8][col] = __floats2bfloat162_rn(e2, e3);
        }

        // copy out previous Es tile (coalesced)
        if (it > 0) {
            const int pe = cur ^ 1;
            const int iprev = (it - 1) * 64;
#pragma unroll
            for (int p = 0; p < 2; p++) {
                int idx = tid + p * 256;
                int r = idx >> 3, q = idx & 7;
                *(uint4*)(Eb + (size_t)r * NN + iprev + q * 8) =
                    *(const uint4*)&Es[pe][r][q * 8];
            }
        }
        // stage next f tile
        if (it + 1 < NIT) {
            int r = tid >> 3, q = tid & 7;
            *(uint4*)&Bfs[cur ^ 1][r][q * 8] = rnext;
        }
        __syncthreads();
    }
    // final Es copy-out
    {
        const int pe = (NIT - 1) & 1;
        const int iprev = (NIT - 1) * 64;
#pragma unroll
        for (int p = 0; p < 2; p++) {
            int idx = tid + p * 256;
            int r = idx >> 3, q = idx & 7;
            *(uint4*)(Eb + (size_t)r * NN + iprev + q * 8) =
                *(const uint4*)&Es[pe][r][q * 8];
        }
    }

    // ---- deterministic Z reduction ----
    zacc0 += __shfl_xor_sync(0xFFFFFFFFu, zacc0, 1);
    zacc0 += __shfl_xor_sync(0xFFFFFFFFu, zacc0, 2);
    zacc1 += __shfl_xor_sync(0xFFFFFFFFu, zacc1, 1);
    zacc1 += __shfl_xor_sync(0xFFFFFFFFu, zacc1, 2);
    if ((l & 3) == 0) {
        int r1 = jr + (l >> 2);
        Zp[cw][r1]     = zacc0;
        Zp[cw][r1 + 8] = zacc1;
    }
    __syncthreads();
    if (tid < 64)
        g_Z[(size_t)b * NN + j0 + tid] = Zp[0][tid] + Zp[1][tid];
}

// ---------------------------------------------------------------------------
// Kernel 3: hb = bf16( hc / Z[j] )
// ---------------------------------------------------------------------------
__global__ void norm_h_kernel()
{
    size_t idx = (size_t)blockIdx.x * blockDim.x + threadIdx.x;  // < B*C*N
    int j = (int)(idx & (NN - 1));
    int b = (int)(idx >> 20);
    float v = __bfloat162float(g_hc[idx]) / g_Z[(size_t)b * NN + j];
    g_hb[idx] = __float2bfloat16(v);
}

// ---------------------------------------------------------------------------
// Kernel 4: out = hb @ E + x.  BM=128, BN=128, BK=64, 2-stage cp.async.
// 256 threads, 8 warps (4 row-groups x 2 col-groups), warp tile 32x64.
// Grid (32, 2, 4) = 256 blocks -> single wave at occupancy 2.
// ---------------------------------------------------------------------------
#define OG_LDA 72
#define OG_LDB 136
#define OG_ASZ (128 * OG_LDA)   // elems per A stage
#define OG_BSZ (64 * OG_LDB)    // elems per B stage
#define OG_SMEM_BYTES ((2 * OG_ASZ + 2 * OG_BSZ) * 2)

__global__ __launch_bounds__(256, 2) void out_gemm_kernel(const float* __restrict__ x,
                                                          float* __restrict__ out)
{
    extern __shared__ char sm[];
    __nv_bfloat16* As = (__nv_bfloat16*)sm;                 // [2][128][72]
    __nv_bfloat16* Bs = As + 2 * OG_ASZ;                    // [2][64][136]

    const int b   = blockIdx.z;
    const int m0  = blockIdx.y * 128;
    const int n0  = blockIdx.x * 128;
    const int tid = threadIdx.x;
    const int w   = tid >> 5;
    const int wr  = w >> 1;       // 0..3  -> rows wr*32
    const int wc  = w & 1;        // 0..1  -> cols wc*64

    const __nv_bfloat16* Ab = g_hb + (size_t)b * CC * NN;
    const __nv_bfloat16* Bb = g_E  + (size_t)b * NN * NN;

    wmma::fragment<wmma::accumulator, 16, 16, 16, float> acc[2][4];
#pragma unroll
    for (int i = 0; i < 2; i++)
#pragma unroll
        for (int j = 0; j < 4; j++)
            wmma::fill_fragment(acc[i][j], 0.0f);

    // cp.async issue helper (stage s, k-offset k0)
    auto issue_stage = [&](int s, int k0) {
        // A: 128 x 64 -> 1024 chunks of 16B, 4 per thread
#pragma unroll
        for (int p = 0; p < 4; p++) {
            int id = tid + p * 256;
            int r = id >> 3, q = id & 7;
            cp_async16(smem_u32(As + s * OG_ASZ + r * OG_LDA + q * 8),
                       Ab + (size_t)(m0 + r) * NN + k0 + q * 8);
        }
        // B: 64 x 128 -> 1024 chunks, 4 per thread
#pragma unroll
        for (int p = 0; p < 4; p++) {
            int id = tid + p * 256;
            int r = id >> 4, q = id & 15;
            cp_async16(smem_u32(Bs + s * OG_BSZ + r * OG_LDB + q * 8),
                       Bb + (size_t)(k0 + r) * NN + n0 + q * 8);
        }
    };

    issue_stage(0, 0);  cp_commit();
    issue_stage(1, 64); cp_commit();

    const int NIT = NN / 64;  // 64
    for (int it = 0; it < NIT; it++) {
        if (it < NIT - 1) cp_wait1(); else cp_wait0();
        __syncthreads();

        const int s = it & 1;
        const __nv_bfloat16* Ast = As + s * OG_ASZ;
        const __nv_bfloat16* Bst = Bs + s * OG_BSZ;
#pragma unroll
        for (int kk = 0; kk < 4; kk++) {
            wmma::fragment<wmma::matrix_a, 16, 16, 16, __nv_bfloat16, wmma::row_major> af[2];
            wmma::fragment<wmma::matrix_b, 16, 16, 16, __nv_bfloat16, wmma::row_major> bf[4];
#pragma unroll
            for (int i = 0; i < 2; i++)
                wmma::load_matrix_sync(af[i], Ast + (wr * 32 + i * 16) * OG_LDA + kk * 16,
                                       OG_LDA);
#pragma unroll
            for (int j = 0; j < 4; j++)
                wmma::load_matrix_sync(bf[j], Bst + (kk * 16) * OG_LDB + wc * 64 + j * 16,
                                       OG_LDB);
#pragma unroll
            for (int i = 0; i < 2; i++)
#pragma unroll
                for (int j = 0; j < 4; j++)
                    wmma::mma_sync(acc[i][j], af[i], bf[j], acc[i][j]);
        }
        __syncthreads();
        if (it + 2 < NIT) { issue_stage(s, (it + 2) * 64); cp_commit(); }
        else              { cp_commit(); }   // keep group count consistent
    }

    // epilogue: out = acc + x
    const float* xb = x   + (size_t)b * CC * NN;
    float*       ob = out + (size_t)b * CC * NN;
#pragma unroll
    for (int i = 0; i < 2; i++) {
#pragma unroll
        for (int j = 0; j < 4; j++) {
            int row = m0 + wr * 32 + i * 16;
            int col = n0 + wc * 64 + j * 16;
            wmma::fragment<wmma::accumulator, 16, 16, 16, float> xf;
            wmma::load_matrix_sync(xf, xb + (size_t)row * NN + col, NN, wmma::mem_row_major);
#pragma unroll
            for (int e = 0; e < xf.num_elements; e++)
                acc[i][j].x[e] += xf.x[e];
            wmma::store_matrix_sync(ob + (size_t)row * NN + col, acc[i][j], NN,
                                    wmma::mem_row_major);
        }
    }
}

// ---------------------------------------------------------------------------
// Launch
// ---------------------------------------------------------------------------
extern "C" void kernel_launch(void* const* d_in, const int* in_sizes, int n_in,
                              void* d_out, int out_size)
{
    const float* x  = (const float*)d_in[0];
    const float* Wf = (const float*)d_in[1];
    const float* bf = (const float*)d_in[2];
    const float* Wg = (const float*)d_in[3];
    const float* bg = (const float*)d_in[4];
    const float* Wh = (const float*)d_in[5];
    const float* bh = (const float*)d_in[6];
    float* out = (float*)d_out;

    // Unconditional (idempotent) — no static guards allowed in kernel_launch.
    cudaFuncSetAttribute(out_gemm_kernel,
                         cudaFuncAttributeMaxDynamicSharedMemorySize, OG_SMEM_BYTES);

    dim3 gFG(NN / 128, 1, BATCH);
    proj_kernel<<<gFG, 128>>>(x, Wf, bf, 0);
    proj_kernel<<<gFG, 128>>>(x, Wg, bg, 1);
    dim3 gH(NN / 128, CC / 32, BATCH);
    proj_kernel<<<gH, 128>>>(x, Wh, bh, 2);

    dim3 gS(NN / 64, BATCH);
    attn_fused_kernel<<<gS, 256>>>();

    norm_h_kernel<<<(BATCH * CC * NN) / 256, 256>>>();

    dim3 gO(NN / 128, CC / 128, BATCH);
    out_gemm_kernel<<<gO, 256, OG_SMEM_BYTES>>>(x, out);
}

// round 7
// speedup vs baseline: 3.1247x; 1.4505x over previous
#include <cuda_runtime.h>
#include <cuda_bf16.h>
#include <mma.h>
#include <cstdint>

using namespace nvcuda;

#define BATCH 4
#define CC    256
#define NN    4096
#define DKK   32

// ---------------------------------------------------------------------------
// Scratch (no g_E anymore — E is never materialized to DRAM)
// ---------------------------------------------------------------------------
__device__ __nv_bfloat16 g_fK[(size_t)BATCH * DKK * NN];   // f  [b][d][n]
__device__ __nv_bfloat16 g_gT[(size_t)BATCH * NN * DKK];   // gT [b][n][d]
__device__ __nv_bfloat16 g_hc[(size_t)BATCH * CC * NN];    // hh [b][c][n] bf16
__device__ __nv_bfloat16 g_hb[(size_t)BATCH * CC * NN];    // hh/Z bf16
__device__ float         g_Z [(size_t)BATCH * NN];         // row sums

// ---------------------------------------------------------------------------
// PTX helpers
// ---------------------------------------------------------------------------
__device__ __forceinline__ uint32_t smem_u32(const void* p) {
    return (uint32_t)__cvta_generic_to_shared(p);
}
__device__ __forceinline__ void ldsm_x4(uint32_t& r0, uint32_t& r1, uint32_t& r2, uint32_t& r3,
                                        uint32_t addr) {
    asm volatile("ldmatrix.sync.aligned.m8n8.x4.shared.b16 {%0,%1,%2,%3}, [%4];"
                 : "=r"(r0), "=r"(r1), "=r"(r2), "=r"(r3) : "r"(addr));
}
__device__ __forceinline__ void ldsm_x2_t(uint32_t& r0, uint32_t& r1, uint32_t addr) {
    asm volatile("ldmatrix.sync.aligned.m8n8.x2.trans.shared.b16 {%0,%1}, [%2];"
                 : "=r"(r0), "=r"(r1) : "r"(addr));
}
__device__ __forceinline__ void mma_16816(float* d, const uint32_t* a, uint32_t b0, uint32_t b1) {
    asm volatile("mma.sync.aligned.m16n8k16.row.col.f32.bf16.bf16.f32 "
                 "{%0,%1,%2,%3}, {%4,%5,%6,%7}, {%8,%9}, {%0,%1,%2,%3};"
                 : "+f"(d[0]), "+f"(d[1]), "+f"(d[2]), "+f"(d[3])
                 : "r"(a[0]), "r"(a[1]), "r"(a[2]), "r"(a[3]), "r"(b0), "r"(b1));
}
__device__ __forceinline__ void cp_async16(uint32_t dst, const void* src) {
    asm volatile("cp.async.cg.shared.global [%0], [%1], 16;" :: "r"(dst), "l"(src));
}
__device__ __forceinline__ void cp_commit() { asm volatile("cp.async.commit_group;"); }
__device__ __forceinline__ void cp_wait1()  { asm volatile("cp.async.wait_group 1;"); }
__device__ __forceinline__ void cp_wait0()  { asm volatile("cp.async.wait_group 0;"); }

// ---------------------------------------------------------------------------
// Kernel 1: all projections in one launch. blockIdx.y routes:
//   y==0: f -> g_fK [d][n];  y==1: g -> g_gT [n][d];  y>=2: hh rows (y-2)*32 -> g_hc
// ---------------------------------------------------------------------------
__global__ void proj_all_kernel(const float* __restrict__ x,
                                const float* __restrict__ Wf, const float* __restrict__ bfp,
                                const float* __restrict__ Wg, const float* __restrict__ bgp,
                                const float* __restrict__ Wh, const float* __restrict__ bhp)
{
    __shared__ __nv_bfloat16 As[32][16];
    __shared__ __nv_bfloat16 Bs[16][128];
    __shared__ float         Cs[32][128];

    const int b   = blockIdx.z;
    const int y   = blockIdx.y;
    const int n0  = blockIdx.x * 128;
    const int tid = threadIdx.x;
    const int warp = tid >> 5;

    const float* W; const float* bias; int mode; int m0;
    if (y == 0)      { W = Wf; bias = bfp; mode = 0; m0 = 0; }
    else if (y == 1) { W = Wg; bias = bgp; mode = 1; m0 = 0; }
    else             { W = Wh; bias = bhp; mode = 2; m0 = (y - 2) * 32; }

    wmma::fragment<wmma::accumulator, 16, 16, 16, float> acc[2][2];
#pragma unroll
    for (int i = 0; i < 2; i++)
#pragma unroll
        for (int j = 0; j < 2; j++)
            wmma::fill_fragment(acc[i][j], 0.0f);

    const float* xb = x + (size_t)b * CC * NN;

    for (int k0 = 0; k0 < CC; k0 += 16) {
        for (int idx = tid; idx < 32 * 16; idx += 128) {
            int r = idx >> 4, c = idx & 15;
            As[r][c] = __float2bfloat16(W[(size_t)(m0 + r) * CC + k0 + c]);
        }
        for (int idx = tid; idx < 16 * 128; idx += 128) {
            int r = idx >> 7, c = idx & 127;
            Bs[r][c] = __float2bfloat16(xb[(size_t)(k0 + r) * NN + n0 + c]);
        }
        __syncthreads();

        wmma::fragment<wmma::matrix_a, 16, 16, 16, __nv_bfloat16, wmma::row_major> af[2];
        wmma::fragment<wmma::matrix_b, 16, 16, 16, __nv_bfloat16, wmma::row_major> bfr[2];
#pragma unroll
        for (int i = 0; i < 2; i++)
            wmma::load_matrix_sync(af[i], &As[i * 16][0], 16);
#pragma unroll
        for (int j = 0; j < 2; j++)
            wmma::load_matrix_sync(bfr[j], &Bs[0][warp * 32 + j * 16], 128);
#pragma unroll
        for (int i = 0; i < 2; i++)
#pragma unroll
            for (int j = 0; j < 2; j++)
                wmma::mma_sync(acc[i][j], af[i], bfr[j], acc[i][j]);
        __syncthreads();
    }

#pragma unroll
    for (int i = 0; i < 2; i++)
#pragma unroll
        for (int j = 0; j < 2; j++)
            wmma::store_matrix_sync(&Cs[i * 16][warp * 32 + j * 16], acc[i][j],
                                    128, wmma::mem_row_major);
    __syncthreads();

    for (int idx = tid; idx < 32 * 128; idx += 128) {
        int r = idx >> 7, c = idx & 127;
        float v = Cs[r][c] + bias[m0 + r];
        if (mode == 0) {
            g_fK[((size_t)b * DKK + r) * NN + n0 + c] = __float2bfloat16(v);
        } else if (mode == 1) {
            g_gT[((size_t)b * NN + (n0 + c)) * DKK + r] = __float2bfloat16(v);
        } else {
            g_hc[((size_t)b * CC + (m0 + r)) * NN + n0 + c] = __float2bfloat16(v);
        }
    }
}

// ---------------------------------------------------------------------------
// Kernel 2: Z only (attn_fused minus E stores). Per block = 64 j-rows.
// ---------------------------------------------------------------------------
__global__ __launch_bounds__(256) void z_kernel()
{
    __shared__ __nv_bfloat16 Ags[64][40];
    __shared__ __nv_bfloat16 Bfs[2][32][72];
    __shared__ float         Zp[2][64];

    const int b   = blockIdx.y;
    const int j0  = blockIdx.x * 64;
    const int tid = threadIdx.x;
    const int w   = tid >> 5;
    const int l   = tid & 31;
    const int jr  = (w >> 1) * 16;
    const int cw  = (w & 1);

    {
        int r = tid >> 2, q = tid & 3;
        *(uint4*)&Ags[r][q * 8] =
            *(const uint4*)(g_gT + ((size_t)b * NN + j0 + r) * DKK + q * 8);
    }
    {
        int r = tid >> 3, q = tid & 7;
        *(uint4*)&Bfs[0][r][q * 8] =
            *(const uint4*)(g_fK + ((size_t)b * DKK + r) * NN + q * 8);
    }
    __syncthreads();

    uint32_t a[2][4];
#pragma unroll
    for (int kf = 0; kf < 2; kf++) {
        uint32_t addr = smem_u32(&Ags[jr + (l & 15)][kf * 16 + (l >> 4) * 8]);
        ldsm_x4(a[kf][0], a[kf][1], a[kf][2], a[kf][3], addr);
    }

    float zacc0 = 0.0f, zacc1 = 0.0f;

    const int NIT = NN / 64;
    for (int it = 0; it < NIT; it++) {
        const int cur = it & 1;
        uint4 rnext;
        if (it + 1 < NIT) {
            int r = tid >> 3, q = tid & 7;
            rnext = *(const uint4*)(g_fK + ((size_t)b * DKK + r) * NN +
                                    (it + 1) * 64 + q * 8);
        }
#pragma unroll
        for (int nf = 0; nf < 4; nf++) {
            const int cb = cw * 32 + nf * 8;
            float d[4] = {0.f, 0.f, 0.f, 0.f};
            uint32_t b0, b1;
            ldsm_x2_t(b0, b1, smem_u32(&Bfs[cur][l & 15][cb]));
            mma_16816(d, a[0], b0, b1);
            ldsm_x2_t(b0, b1, smem_u32(&Bfs[cur][16 + (l & 15)][cb]));
            mma_16816(d, a[1], b0, b1);
            zacc0 += __expf(d[0]) + __expf(d[1]);
            zacc1 += __expf(d[2]) + __expf(d[3]);
        }
        if (it + 1 < NIT) {
            int r = tid >> 3, q = tid & 7;
            *(uint4*)&Bfs[cur ^ 1][r][q * 8] = rnext;
        }
        __syncthreads();
    }

    zacc0 += __shfl_xor_sync(0xFFFFFFFFu, zacc0, 1);
    zacc0 += __shfl_xor_sync(0xFFFFFFFFu, zacc0, 2);
    zacc1 += __shfl_xor_sync(0xFFFFFFFFu, zacc1, 1);
    zacc1 += __shfl_xor_sync(0xFFFFFFFFu, zacc1, 2);
    if ((l & 3) == 0) {
        int r1 = jr + (l >> 2);
        Zp[cw][r1]     = zacc0;
        Zp[cw][r1 + 8] = zacc1;
    }
    __syncthreads();
    if (tid < 64)
        g_Z[(size_t)b * NN + j0 + tid] = Zp[0][tid] + Zp[1][tid];
}

// ---------------------------------------------------------------------------
// Kernel 3: hb = bf16( hc / Z[j] )
// ---------------------------------------------------------------------------
__global__ void norm_h_kernel()
{
    size_t idx = (size_t)blockIdx.x * blockDim.x + threadIdx.x;
    int j = (int)(idx & (NN - 1));
    int b = (int)(idx >> 20);
    float v = __bfloat162float(g_hc[idx]) / g_Z[(size_t)b * NN + j];
    g_hb[idx] = __float2bfloat16(v);
}

// ---------------------------------------------------------------------------
// Kernel 4 (fully fused): out[:, i_tile] = sum_j hb[:, j] * exp(gT_j @ f_iTile) + x
// Per CTA: batch b, 128-col i-tile, full 256-row o accumulator in registers.
// 512 threads = 16 warps.
//   E-compute role: warp rows (w&3)*16, cols (w>>2)*32 of the 64x128 E tile.
//   o-GEMM role:    warp rows (w>>1)*32, cols (w&1)*64 of the 256x128 o tile.
// gT/hb staged with 3-buffer cp.async (depth 2). E tile lives only in smem.
// ---------------------------------------------------------------------------
#define FO_LDF 136
#define FO_LDG 40
#define FO_LDE 136
#define FO_LDH 72
#define FO_F_ELEMS   (32 * FO_LDF)          // 4352
#define FO_G_STG     (64 * FO_LDG)          // 2560 per stage
#define FO_E_ELEMS   (64 * FO_LDE)          // 8704
#define FO_H_STG     (256 * FO_LDH)         // 18432 per stage
#define FO_SMEM_ELEMS (FO_F_ELEMS + 3 * FO_G_STG + FO_E_ELEMS + 3 * FO_H_STG)
#define FO_SMEM_BYTES (FO_SMEM_ELEMS * 2)   // 152064 bytes

__global__ __launch_bounds__(512) void fused_out_kernel(const float* __restrict__ x,
                                                        float* __restrict__ out)
{
    extern __shared__ __nv_bfloat16 sm[];
    __nv_bfloat16* f_s  = sm;                          // [32][136]
    __nv_bfloat16* gT_s = f_s + FO_F_ELEMS;            // [3][64][40]
    __nv_bfloat16* E_s  = gT_s + 3 * FO_G_STG;         // [64][136]
    __nv_bfloat16* hb_s = E_s + FO_E_ELEMS;            // [3][256][72]

    const int b   = blockIdx.y;
    const int i0  = blockIdx.x * 128;
    const int tid = threadIdx.x;
    const int w   = tid >> 5;
    const int l   = tid & 31;

    const int re = (w & 3) * 16;    // E-compute row base
    const int ce = (w >> 2);        // E-compute col group (*32)
    const int rw = (w >> 1);        // o row group (*32)
    const int cg = (w & 1);         // o col group (*64)

    const __nv_bfloat16* fKb = g_fK + (size_t)b * DKK * NN;
    const __nv_bfloat16* gTb = g_gT + (size_t)b * NN * DKK;
    const __nv_bfloat16* hbb = g_hb + (size_t)b * CC * NN;

    // ---- load f tile [32][128] (plain stores) ----
    {
        int r = tid >> 4, q = tid & 15;
        *(uint4*)(f_s + r * FO_LDF + q * 8) =
            *(const uint4*)(fKb + (size_t)r * NN + i0 + q * 8);
    }

    // ---- cp.async stage issue: gT[64x32] + hb[256x64] for j-tile jt into buffer bi
    auto issue_stage = [&](int jt, int bi) {
        int j0s = jt * 64;
        if (tid < 256) {
            int r = tid >> 2, q = tid & 3;
            cp_async16(smem_u32(gT_s + bi * FO_G_STG + r * FO_LDG + q * 8),
                       gTb + (size_t)(j0s + r) * DKK + q * 8);
        }
#pragma unroll
        for (int p = 0; p < 4; p++) {
            int id = tid + p * 512;
            int r = id >> 3, q = id & 7;
            cp_async16(smem_u32(hb_s + bi * FO_H_STG + r * FO_LDH + q * 8),
                       hbb + (size_t)r * NN + j0s + q * 8);
        }
    };

    issue_stage(0, 0); cp_commit();
    issue_stage(1, 1); cp_commit();

    cp_wait1();
    __syncthreads();   // f_s + stage0 visible

    // ---- preload f B-fragments (fixed for whole kernel) ----
    uint32_t bf_f[2][4][2];
#pragma unroll
    for (int kd = 0; kd < 2; kd++)
#pragma unroll
        for (int nf = 0; nf < 4; nf++)
            ldsm_x2_t(bf_f[kd][nf][0], bf_f[kd][nf][1],
                      smem_u32(f_s + (kd * 16 + (l & 15)) * FO_LDF + ce * 32 + nf * 8));

    float acc[2][8][4];
#pragma unroll
    for (int mi = 0; mi < 2; mi++)
#pragma unroll
        for (int n8 = 0; n8 < 8; n8++)
#pragma unroll
            for (int e = 0; e < 4; e++)
                acc[mi][n8][e] = 0.0f;

    const int NIT = NN / 64;   // 64
    for (int it = 0; it < NIT; it++) {
        const int s3 = it % 3;
        if (it > 0) {           // it==0 already waited above
            if (it < NIT - 1) cp_wait1(); else cp_wait0();
            __syncthreads();    // stage s3 visible; prev o-GEMM done (E_s free)
        }

        // ---- E-compute: E_s = exp(gT_j @ f) ----
        uint32_t aG[2][4];
#pragma unroll
        for (int kd = 0; kd < 2; kd++)
            ldsm_x4(aG[kd][0], aG[kd][1], aG[kd][2], aG[kd][3],
                    smem_u32(gT_s + s3 * FO_G_STG + (re + (l & 15)) * FO_LDG +
                             kd * 16 + (l >> 4) * 8));
#pragma unroll
        for (int nf = 0; nf < 4; nf++) {
            float d[4] = {0.f, 0.f, 0.f, 0.f};
            mma_16816(d, aG[0], bf_f[0][nf][0], bf_f[0][nf][1]);
            mma_16816(d, aG[1], bf_f[1][nf][0], bf_f[1][nf][1]);
            float e0 = __expf(d[0]), e1 = __expf(d[1]);
            float e2 = __expf(d[2]), e3 = __expf(d[3]);
            int r1  = re + (l >> 2);
            int col = ce * 32 + nf * 8 + (l & 3) * 2;
            *(__nv_bfloat162*)(E_s + (size_t)r1 * FO_LDE + col)       = __floats2bfloat162_rn(e0, e1);
            *(__nv_bfloat162*)(E_s + (size_t)(r1 + 8) * FO_LDE + col) = __floats2bfloat162_rn(e2, e3);
        }
        __syncthreads();        // E_s visible to all warps

        // ---- issue prefetch for it+2 into buffer (it+2)%3 (not referenced this iter)
        if (it + 2 < NIT) issue_stage(it + 2, (it + 2) % 3);
        cp_commit();

        // ---- o-GEMM: acc += hb_tile @ E_s ----
#pragma unroll
        for (int kk = 0; kk < 4; kk++) {
            uint32_t aH[2][4];
#pragma unroll
            for (int mi = 0; mi < 2; mi++)
                ldsm_x4(aH[mi][0], aH[mi][1], aH[mi][2], aH[mi][3],
                        smem_u32(hb_s + s3 * FO_H_STG +
                                 (rw * 32 + mi * 16 + (l & 15)) * FO_LDH +
                                 kk * 16 + (l >> 4) * 8));
#pragma unroll
            for (int n8 = 0; n8 < 8; n8++) {
                uint32_t b0, b1;
                ldsm_x2_t(b0, b1, smem_u32(E_s + (size_t)(kk * 16 + (l & 15)) * FO_LDE +
                                           cg * 64 + n8 * 8));
                mma_16816(acc[0][n8], aH[0], b0, b1);
                mma_16816(acc[1][n8], aH[1], b0, b1);
            }
        }
        __syncthreads();        // all reads of stage s3 + E_s done before next write
    }

    // ---- epilogue: out = acc + x ----
    const float* xb = x   + (size_t)b * CC * NN;
    float*       ob = out + (size_t)b * CC * NN;
#pragma unroll
    for (int mi = 0; mi < 2; mi++) {
#pragma unroll
        for (int n8 = 0; n8 < 8; n8++) {
            int row0 = rw * 32 + mi * 16 + (l >> 2);
            int col  = i0 + cg * 64 + n8 * 8 + (l & 3) * 2;
            float2 xv0 = *(const float2*)(xb + (size_t)row0 * NN + col);
            float2 o0  = make_float2(acc[mi][n8][0] + xv0.x, acc[mi][n8][1] + xv0.y);
            *(float2*)(ob + (size_t)row0 * NN + col) = o0;
            float2 xv1 = *(const float2*)(xb + (size_t)(row0 + 8) * NN + col);
            float2 o1  = make_float2(acc[mi][n8][2] + xv1.x, acc[mi][n8][3] + xv1.y);
            *(float2*)(ob + (size_t)(row0 + 8) * NN + col) = o1;
        }
    }
}

// ---------------------------------------------------------------------------
// Launch
// ---------------------------------------------------------------------------
extern "C" void kernel_launch(void* const* d_in, const int* in_sizes, int n_in,
                              void* d_out, int out_size)
{
    const float* x  = (const float*)d_in[0];
    const float* Wf = (const float*)d_in[1];
    const float* bf = (const float*)d_in[2];
    const float* Wg = (const float*)d_in[3];
    const float* bg = (const float*)d_in[4];
    const float* Wh = (const float*)d_in[5];
    const float* bh = (const float*)d_in[6];
    float* out = (float*)d_out;

    cudaFuncSetAttribute(fused_out_kernel,
                         cudaFuncAttributeMaxDynamicSharedMemorySize, FO_SMEM_BYTES);

    // all projections in one launch: y=0 f, y=1 g, y=2..9 hh tiles
    dim3 gP(NN / 128, 2 + CC / 32, BATCH);
    proj_all_kernel<<<gP, 128>>>(x, Wf, bf, Wg, bg, Wh, bh);

    dim3 gZ(NN / 64, BATCH);
    z_kernel<<<gZ, 256>>>();

    norm_h_kernel<<<(BATCH * CC * NN) / 256, 256>>>();

    dim3 gO(NN / 128, BATCH);
    fused_out_kernel<<<gO, 512, FO_SMEM_BYTES>>>(x, out);
}

// round 13
// speedup vs baseline: 3.4136x; 1.0924x over previous
#include <cuda_runtime.h>
#include <cuda_bf16.h>
#include <cstdint>

#define BATCH 4
#define CC    256
#define NN    4096
#define DKK   32

// ---------------------------------------------------------------------------
// Scratch
// ---------------------------------------------------------------------------
__device__ __nv_bfloat16 g_fK[(size_t)BATCH * DKK * NN];   // f  [b][d][n]
__device__ __nv_bfloat16 g_gT[(size_t)BATCH * NN * DKK];   // gT [b][n][d]
__device__ __nv_bfloat16 g_hc[(size_t)BATCH * CC * NN];    // hh [b][c][n] bf16
__device__ __nv_bfloat16 g_xb[(size_t)BATCH * CC * NN];    // x  bf16
__device__ float         g_Z [(size_t)BATCH * NN];         // RECIPROCAL row sums

// ---------------------------------------------------------------------------
// PTX helpers
// ---------------------------------------------------------------------------
__device__ __forceinline__ uint32_t smem_u32(const void* p) {
    return (uint32_t)__cvta_generic_to_shared(p);
}
__device__ __forceinline__ void ldsm_x4(uint32_t& r0, uint32_t& r1, uint32_t& r2, uint32_t& r3,
                                        uint32_t addr) {
    asm volatile("ldmatrix.sync.aligned.m8n8.x4.shared.b16 {%0,%1,%2,%3}, [%4];"
                 : "=r"(r0), "=r"(r1), "=r"(r2), "=r"(r3) : "r"(addr));
}
__device__ __forceinline__ void ldsm_x2_t(uint32_t& r0, uint32_t& r1, uint32_t addr) {
    asm volatile("ldmatrix.sync.aligned.m8n8.x2.trans.shared.b16 {%0,%1}, [%2];"
                 : "=r"(r0), "=r"(r1) : "r"(addr));
}
__device__ __forceinline__ void mma_16816(float* d, const uint32_t* a, uint32_t b0, uint32_t b1) {
    asm volatile("mma.sync.aligned.m16n8k16.row.col.f32.bf16.bf16.f32 "
                 "{%0,%1,%2,%3}, {%4,%5,%6,%7}, {%8,%9}, {%0,%1,%2,%3};"
                 : "+f"(d[0]), "+f"(d[1]), "+f"(d[2]), "+f"(d[3])
                 : "r"(a[0]), "r"(a[1]), "r"(a[2]), "r"(a[3]), "r"(b0), "r"(b1));
}
__device__ __forceinline__ void cp_async16(uint32_t dst, const void* src) {
    asm volatile("cp.async.cg.shared.global [%0], [%1], 16;" :: "r"(dst), "l"(src));
}
__device__ __forceinline__ void cp_commit() { asm volatile("cp.async.commit_group;"); }
__device__ __forceinline__ void cp_wait1()  { asm volatile("cp.async.wait_group 1;"); }
__device__ __forceinline__ void cp_wait0()  { asm volatile("cp.async.wait_group 0;"); }

// ---------------------------------------------------------------------------
// Kernel 0: x -> bf16 (g_xb). 8 elems/thread.
// ---------------------------------------------------------------------------
__global__ void xcvt_kernel(const float* __restrict__ x)
{
    size_t i8 = ((size_t)blockIdx.x * 256 + threadIdx.x) * 8;
    float4 a = *(const float4*)(x + i8);
    float4 c = *(const float4*)(x + i8 + 4);
    __nv_bfloat162 o[4];
    o[0] = __floats2bfloat162_rn(a.x, a.y);
    o[1] = __floats2bfloat162_rn(a.z, a.w);
    o[2] = __floats2bfloat162_rn(c.x, c.y);
    o[3] = __floats2bfloat162_rn(c.z, c.w);
    *(uint4*)(g_xb + i8) = *(uint4*)o;
}

// ---------------------------------------------------------------------------
// Kernel 1: unified projection GEMM over concatenated [Wf;Wg;Wh] (320 rows).
// blockIdx.y: 0 -> rows [f(32); g(32)], 1..4 -> Wh rows (y-1)*64.
// BM=64, BN=128, BK=32, 256 threads (8 warps: rows (w>>1)*16, cols (w&1)*64).
// W converted fp32->bf16 into smem once; x tiles via 2-stage cp.async (bf16).
// ---------------------------------------------------------------------------
#define P2_LDW 264
#define P2_LDX 136
#define P2_W_ELEMS (64 * P2_LDW)
#define P2_X_STG   (32 * P2_LDX)
#define P2_SMEM_BYTES ((P2_W_ELEMS + 2 * P2_X_STG) * 2 + 64 * 4)

__global__ __launch_bounds__(256) void proj2_kernel(
    const float* __restrict__ Wf, const float* __restrict__ bfp,
    const float* __restrict__ Wg, const float* __restrict__ bgp,
    const float* __restrict__ Wh, const float* __restrict__ bhp)
{
    extern __shared__ __nv_bfloat16 sm[];
    __nv_bfloat16* Wt = sm;                        // [64][264]
    __nv_bfloat16* xs = Wt + P2_W_ELEMS;           // [2][32][136]
    float* bias_s = (float*)(xs + 2 * P2_X_STG);   // [64]

    const int b   = blockIdx.z;
    const int y   = blockIdx.y;
    const int n0  = blockIdx.x * 128;
    const int tid = threadIdx.x;
    const int w   = tid >> 5;
    const int l   = tid & 31;
    const int rw  = (w >> 1);      // row group *16
    const int cg  = (w & 1);       // col group *64

    // ---- convert W m-tile + bias to smem ----
    for (int idx = tid; idx < 64 * 256; idx += 256) {
        int r = idx >> 8, c = idx & 255;
        float v;
        if (y == 0) v = (r < 32) ? Wf[r * CC + c] : Wg[(r - 32) * CC + c];
        else        v = Wh[((size_t)((y - 1) * 64 + r)) * CC + c];
        Wt[r * P2_LDW + c] = __float2bfloat16(v);
    }
    if (tid < 64) {
        float bv;
        if (y == 0) bv = (tid < 32) ? bfp[tid] : bgp[tid - 32];
        else        bv = bhp[(y - 1) * 64 + tid];
        bias_s[tid] = bv;
    }

    const __nv_bfloat16* xbb = g_xb + (size_t)b * CC * NN;

    auto issue_x = [&](int kt, int s) {
        int k0 = kt * 32;
#pragma unroll
        for (int p = 0; p < 2; p++) {
            int id = tid + p * 256;
            int r = id >> 4, q = id & 15;
            cp_async16(smem_u32(xs + s * P2_X_STG + r * P2_LDX + q * 8),
                       xbb + (size_t)(k0 + r) * NN + n0 + q * 8);
        }
    };

    issue_x(0, 0); cp_commit();
    issue_x(1, 1); cp_commit();

    float acc[8][4];
#pragma unroll
    for (int n8 = 0; n8 < 8; n8++)
#pragma unroll
        for (int e = 0; e < 4; e++) acc[n8][e] = 0.0f;

    const int NIT = CC / 32;   // 8
    for (int it = 0; it < NIT; it++) {
        if (it < NIT - 1) cp_wait1(); else cp_wait0();
        __syncthreads();
        const int s = it & 1;
#pragma unroll
        for (int kd = 0; kd < 2; kd++) {
            uint32_t aW[4];
            ldsm_x4(aW[0], aW[1], aW[2], aW[3],
                    smem_u32(Wt + (rw * 16 + (l & 15)) * P2_LDW +
                             it * 32 + kd * 16 + (l >> 4) * 8));
#pragma unroll
            for (int n8 = 0; n8 < 8; n8++) {
                uint32_t b0, b1;
                ldsm_x2_t(b0, b1, smem_u32(xs + s * P2_X_STG +
                                           (kd * 16 + (l & 15)) * P2_LDX +
                                           cg * 64 + n8 * 8));
                mma_16816(acc[n8], aW, b0, b1);
            }
        }
        __syncthreads();
        if (it + 2 < NIT) { issue_x(it + 2, s); cp_commit(); }
        else              { cp_commit(); }
    }

    // ---- epilogue + routing ----
#pragma unroll
    for (int n8 = 0; n8 < 8; n8++) {
        int ml0 = rw * 16 + (l >> 2);
        int col = n0 + cg * 64 + n8 * 8 + (l & 3) * 2;
#pragma unroll
        for (int half = 0; half < 2; half++) {
            int ml = ml0 + half * 8;
            float v0 = acc[n8][half * 2 + 0] + bias_s[ml];
            float v1 = acc[n8][half * 2 + 1] + bias_s[ml];
            if (y == 0) {
                if (ml < 32) {
                    *(__nv_bfloat162*)(g_fK + ((size_t)b * DKK + ml) * NN + col) =
                        __floats2bfloat162_rn(v0, v1);
                } else {
                    int d = ml - 32;
                    g_gT[((size_t)b * NN + col)     * DKK + d] = __float2bfloat16(v0);
                    g_gT[((size_t)b * NN + col + 1) * DKK + d] = __float2bfloat16(v1);
                }
            } else {
                int hr = (y - 1) * 64 + ml;
                *(__nv_bfloat162*)(g_hc + ((size_t)b * CC + hr) * NN + col) =
                    __floats2bfloat162_rn(v0, v1);
            }
        }
    }
}

// ---------------------------------------------------------------------------
// Kernel 2: reciprocal row sums.  g_Z[b][j] = 1 / sum_i exp(s[j,i])
// ---------------------------------------------------------------------------
__global__ __launch_bounds__(256) void z_kernel()
{
    __shared__ __nv_bfloat16 Ags[64][40];
    __shared__ __nv_bfloat16 Bfs[2][32][72];
    __shared__ float         Zp[2][64];

    const int b   = blockIdx.y;
    const int j0  = blockIdx.x * 64;
    const int tid = threadIdx.x;
    const int w   = tid >> 5;
    const int l   = tid & 31;
    const int jr  = (w >> 1) * 16;
    const int cw  = (w & 1);

    {
        int r = tid >> 2, q = tid & 3;
        *(uint4*)&Ags[r][q * 8] =
            *(const uint4*)(g_gT + ((size_t)b * NN + j0 + r) * DKK + q * 8);
    }
    {
        int r = tid >> 3, q = tid & 7;
        *(uint4*)&Bfs[0][r][q * 8] =
            *(const uint4*)(g_fK + ((size_t)b * DKK + r) * NN + q * 8);
    }
    __syncthreads();

    uint32_t a[2][4];
#pragma unroll
    for (int kf = 0; kf < 2; kf++) {
        uint32_t addr = smem_u32(&Ags[jr + (l & 15)][kf * 16 + (l >> 4) * 8]);
        ldsm_x4(a[kf][0], a[kf][1], a[kf][2], a[kf][3], addr);
    }

    float zacc0 = 0.0f, zacc1 = 0.0f;

    const int NIT = NN / 64;
    for (int it = 0; it < NIT; it++) {
        const int cur = it & 1;
        uint4 rnext;
        if (it + 1 < NIT) {
            int r = tid >> 3, q = tid & 7;
            rnext = *(const uint4*)(g_fK + ((size_t)b * DKK + r) * NN +
                                    (it + 1) * 64 + q * 8);
        }
#pragma unroll
        for (int nf = 0; nf < 4; nf++) {
            const int cb = cw * 32 + nf * 8;
            float d[4] = {0.f, 0.f, 0.f, 0.f};
            uint32_t b0, b1;
            ldsm_x2_t(b0, b1, smem_u32(&Bfs[cur][l & 15][cb]));
            mma_16816(d, a[0], b0, b1);
            ldsm_x2_t(b0, b1, smem_u32(&Bfs[cur][16 + (l & 15)][cb]));
            mma_16816(d, a[1], b0, b1);
            zacc0 += __expf(d[0]) + __expf(d[1]);
            zacc1 += __expf(d[2]) + __expf(d[3]);
        }
        if (it + 1 < NIT) {
            int r = tid >> 3, q = tid & 7;
            *(uint4*)&Bfs[cur ^ 1][r][q * 8] = rnext;
        }
        __syncthreads();
    }

    zacc0 += __shfl_xor_sync(0xFFFFFFFFu, zacc0, 1);
    zacc0 += __shfl_xor_sync(0xFFFFFFFFu, zacc0, 2);
    zacc1 += __shfl_xor_sync(0xFFFFFFFFu, zacc1, 1);
    zacc1 += __shfl_xor_sync(0xFFFFFFFFu, zacc1, 2);
    if ((l & 3) == 0) {
        int r1 = jr + (l >> 2);
        Zp[cw][r1]     = zacc0;
        Zp[cw][r1 + 8] = zacc1;
    }
    __syncthreads();
    if (tid < 64)
        g_Z[(size_t)b * NN + j0 + tid] = 1.0f / (Zp[0][tid] + Zp[1][tid]);
}

// ---------------------------------------------------------------------------
// Kernel 3 (fused): out[c_half, i_tile] = sum_j hc[:,j] * (exp(gT_j @ f_i)*rZ_j) + x
// Per CTA: 128 c-rows x 128 i-cols; 256 threads (8 warps), 2 CTAs/SM.
//   E role: warp w -> rows (w&3)*16, cols (w>>2)*64 of 64x128 E tile.
//   o role: warp w -> rows (w>>1)*32, cols (w&1)*64 of 128x128 o tile.
// ---------------------------------------------------------------------------
#define FO_LDF 136
#define FO_LDG 40
#define FO_LDE 136
#define FO_LDH 72
#define FO_F_ELEMS   (32 * FO_LDF)
#define FO_G_STG     (64 * FO_LDG)
#define FO_E_ELEMS   (64 * FO_LDE)
#define FO_H_STG     (128 * FO_LDH)
#define FO_SMEM_ELEMS (FO_F_ELEMS + 3 * FO_G_STG + FO_E_ELEMS + 3 * FO_H_STG)
#define FO_SMEM_BYTES (FO_SMEM_ELEMS * 2)   // 96768 bytes

__global__ __launch_bounds__(256, 2) void fused_out_kernel(const float* __restrict__ x,
                                                           float* __restrict__ out)
{
    extern __shared__ __nv_bfloat16 smf[];
    __nv_bfloat16* f_s  = smf;                         // [32][136]
    __nv_bfloat16* gT_s = f_s + FO_F_ELEMS;            // [3][64][40]
    __nv_bfloat16* E_s  = gT_s + 3 * FO_G_STG;         // [64][136]
    __nv_bfloat16* hc_s = E_s + FO_E_ELEMS;            // [3][128][72]

    const int b   = blockIdx.z;
    const int c0  = blockIdx.y * 128;
    const int i0  = blockIdx.x * 128;
    const int tid = threadIdx.x;
    const int w   = tid >> 5;
    const int l   = tid & 31;

    const int re = (w & 3) * 16;    // E rows
    const int ce = (w >> 2);        // E col group (*64)
    const int rw = (w >> 1);        // o row group (*32)
    const int cg = (w & 1);         // o col group (*64)

    const __nv_bfloat16* fKb = g_fK + (size_t)b * DKK * NN;
    const __nv_bfloat16* gTb = g_gT + (size_t)b * NN * DKK;
    const __nv_bfloat16* hcb = g_hc + (size_t)b * CC * NN + (size_t)c0 * NN;
    const float*         rZb = g_Z  + (size_t)b * NN;

    // ---- f tile [32][128] (plain stores) ----
#pragma unroll
    for (int p = 0; p < 2; p++) {
        int id = tid + p * 256;
        int r = id >> 4, q = id & 15;
        *(uint4*)(f_s + r * FO_LDF + q * 8) =
            *(const uint4*)(fKb + (size_t)r * NN + i0 + q * 8);
    }

    auto issue_stage = [&](int jt, int bi) {
        int j0s = jt * 64;
        {
            int r = tid >> 2, q = tid & 3;
            cp_async16(smem_u32(gT_s + bi * FO_G_STG + r * FO_LDG + q * 8),
                       gTb + (size_t)(j0s + r) * DKK + q * 8);
        }
#pragma unroll
        for (int p = 0; p < 4; p++) {
            int id = tid + p * 256;
            int r = id >> 3, q = id & 7;
            cp_async16(smem_u32(hc_s + bi * FO_H_STG + r * FO_LDH + q * 8),
                       hcb + (size_t)r * NN + j0s + q * 8);
        }
    };

    issue_stage(0, 0); cp_commit();
    issue_stage(1, 1); cp_commit();

    cp_wait1();
    __syncthreads();

    float acc[2][8][4];
#pragma unroll
    for (int mi = 0; mi < 2; mi++)
#pragma unroll
        for (int n8 = 0; n8 < 8; n8++)
#pragma unroll
            for (int e = 0; e < 4; e++) acc[mi][n8][e] = 0.0f;

    const int NIT = NN / 64;   // 64
    for (int it = 0; it < NIT; it++) {
        const int s3 = it % 3;
        if (it > 0) {
            if (it < NIT - 1) cp_wait1(); else cp_wait0();
            __syncthreads();
        }

        // ---- E-compute: E_s = exp(gT_j @ f) * rZ_j ----
        {
            const int j0s = it * 64;
            const int r1  = re + (l >> 2);
            const float rzA = __ldg(rZb + j0s + r1);
            const float rzB = __ldg(rZb + j0s + r1 + 8);
            uint32_t aG[2][4];
#pragma unroll
            for (int kd = 0; kd < 2; kd++)
                ldsm_x4(aG[kd][0], aG[kd][1], aG[kd][2], aG[kd][3],
                        smem_u32(gT_s + s3 * FO_G_STG + (re + (l & 15)) * FO_LDG +
                                 kd * 16 + (l >> 4) * 8));
#pragma unroll
            for (int nf = 0; nf < 8; nf++) {
                const int col8 = ce * 64 + nf * 8;
                float d[4] = {0.f, 0.f, 0.f, 0.f};
                uint32_t b0, b1;
                ldsm_x2_t(b0, b1, smem_u32(f_s + (l & 15) * FO_LDF + col8));
                mma_16816(d, aG[0], b0, b1);
                ldsm_x2_t(b0, b1, smem_u32(f_s + (16 + (l & 15)) * FO_LDF + col8));
                mma_16816(d, aG[1], b0, b1);
                float e0 = __expf(d[0]) * rzA, e1 = __expf(d[1]) * rzA;
                float e2 = __expf(d[2]) * rzB, e3 = __expf(d[3]) * rzB;
                int col = col8 + (l & 3) * 2;
                *(__nv_bfloat162*)(E_s + (size_t)r1 * FO_LDE + col)       = __floats2bfloat162_rn(e0, e1);
                *(__nv_bfloat162*)(E_s + (size_t)(r1 + 8) * FO_LDE + col) = __floats2bfloat162_rn(e2, e3);
            }
        }
        __syncthreads();

        if (it + 2 < NIT) issue_stage(it + 2, (it + 2) % 3);
        cp_commit();

        // ---- o-GEMM: acc += hc_tile @ E_s ----
#pragma unroll
        for (int kk = 0; kk < 4; kk++) {
            uint32_t aH[2][4];
#pragma unroll
            for (int mi = 0; mi < 2; mi++)
                ldsm_x4(aH[mi][0], aH[mi][1], aH[mi][2], aH[mi][3],
                        smem_u32(hc_s + s3 * FO_H_STG +
                                 (rw * 32 + mi * 16 + (l & 15)) * FO_LDH +
                                 kk * 16 + (l >> 4) * 8));
#pragma unroll
            for (int n8 = 0; n8 < 8; n8++) {
                uint32_t b0, b1;
                ldsm_x2_t(b0, b1, smem_u32(E_s + (size_t)(kk * 16 + (l & 15)) * FO_LDE +
                                           cg * 64 + n8 * 8));
                mma_16816(acc[0][n8], aH[0], b0, b1);
                mma_16816(acc[1][n8], aH[1], b0, b1);
            }
        }
        __syncthreads();
    }

    // ---- epilogue: out = acc + x ----
    const float* xb = x   + (size_t)b * CC * NN + (size_t)c0 * NN;
    float*       ob = out + (size_t)b * CC * NN + (size_t)c0 * NN;
#pragma unroll
    for (int mi = 0; mi < 2; mi++) {
#pragma unroll
        for (int n8 = 0; n8 < 8; n8++) {
            int row0 = rw * 32 + mi * 16 + (l >> 2);
            int col  = i0 + cg * 64 + n8 * 8 + (l & 3) * 2;
            float2 xv0 = *(const float2*)(xb + (size_t)row0 * NN + col);
            *(float2*)(ob + (size_t)row0 * NN + col) =
                make_float2(acc[mi][n8][0] + xv0.x, acc[mi][n8][1] + xv0.y);
            float2 xv1 = *(const float2*)(xb + (size_t)(row0 + 8) * NN + col);
            *(float2*)(ob + (size_t)(row0 + 8) * NN + col) =
                make_float2(acc[mi][n8][2] + xv1.x, acc[mi][n8][3] + xv1.y);
        }
    }
}

// ---------------------------------------------------------------------------
// Launch
// ---------------------------------------------------------------------------
extern "C" void kernel_launch(void* const* d_in, const int* in_sizes, int n_in,
                              void* d_out, int out_size)
{
    const float* x  = (const float*)d_in[0];
    const float* Wf = (const float*)d_in[1];
    const float* bf = (const float*)d_in[2];
    const float* Wg = (const float*)d_in[3];
    const float* bg = (const float*)d_in[4];
    const float* Wh = (const float*)d_in[5];
    const float* bh = (const float*)d_in[6];
    float* out = (float*)d_out;

    cudaFuncSetAttribute(proj2_kernel,
                         cudaFuncAttributeMaxDynamicSharedMemorySize, P2_SMEM_BYTES);
    cudaFuncSetAttribute(fused_out_kernel,
                         cudaFuncAttributeMaxDynamicSharedMemorySize, FO_SMEM_BYTES);

    xcvt_kernel<<<(BATCH * CC * NN) / (256 * 8), 256>>>(x);

    dim3 gP(NN / 128, 5, BATCH);
    proj2_kernel<<<gP, 256, P2_SMEM_BYTES>>>(Wf, bf, Wg, bg, Wh, bh);

    dim3 gZ(NN / 64, BATCH);
    z_kernel<<<gZ, 256>>>();

    dim3 gO(NN / 128, 2, BATCH);
    fused_out_kernel<<<gO, 256, FO_SMEM_BYTES>>>(x, out);
}

// round 16
// speedup vs baseline: 4.1206x; 1.2071x over previous
#include <cuda_runtime.h>
#include <cuda_bf16.h>
#include <cstdint>

#define BATCH 4
#define CC    256
#define NN    4096
#define DKK   32

// ---------------------------------------------------------------------------
// Scratch
// ---------------------------------------------------------------------------
__device__ __nv_bfloat16 g_fK[(size_t)BATCH * DKK * NN];   // f  [b][d][n]
__device__ __nv_bfloat16 g_gT[(size_t)BATCH * NN * DKK];   // gT [b][n][d]
__device__ __nv_bfloat16 g_hc[(size_t)BATCH * CC * NN];    // hh [b][c][n] bf16
__device__ __nv_bfloat16 g_xb[(size_t)BATCH * CC * NN];    // x  bf16
__device__ float         g_Z [(size_t)BATCH * NN];         // RECIPROCAL row sums

// ---------------------------------------------------------------------------
// PTX helpers
// ---------------------------------------------------------------------------
__device__ __forceinline__ uint32_t smem_u32(const void* p) {
    return (uint32_t)__cvta_generic_to_shared(p);
}
__device__ __forceinline__ void ldsm_x4(uint32_t& r0, uint32_t& r1, uint32_t& r2, uint32_t& r3,
                                        uint32_t addr) {
    asm volatile("ldmatrix.sync.aligned.m8n8.x4.shared.b16 {%0,%1,%2,%3}, [%4];"
                 : "=r"(r0), "=r"(r1), "=r"(r2), "=r"(r3) : "r"(addr));
}
__device__ __forceinline__ void ldsm_x2_t(uint32_t& r0, uint32_t& r1, uint32_t addr) {
    asm volatile("ldmatrix.sync.aligned.m8n8.x2.trans.shared.b16 {%0,%1}, [%2];"
                 : "=r"(r0), "=r"(r1) : "r"(addr));
}
__device__ __forceinline__ void mma_16816(float* d, const uint32_t* a, uint32_t b0, uint32_t b1) {
    asm volatile("mma.sync.aligned.m16n8k16.row.col.f32.bf16.bf16.f32 "
                 "{%0,%1,%2,%3}, {%4,%5,%6,%7}, {%8,%9}, {%0,%1,%2,%3};"
                 : "+f"(d[0]), "+f"(d[1]), "+f"(d[2]), "+f"(d[3])
                 : "r"(a[0]), "r"(a[1]), "r"(a[2]), "r"(a[3]), "r"(b0), "r"(b1));
}
__device__ __forceinline__ void cp_async16(uint32_t dst, const void* src) {
    asm volatile("cp.async.cg.shared.global [%0], [%1], 16;" :: "r"(dst), "l"(src));
}
__device__ __forceinline__ void cp_commit() { asm volatile("cp.async.commit_group;"); }
__device__ __forceinline__ void cp_wait1()  { asm volatile("cp.async.wait_group 1;"); }
__device__ __forceinline__ void cp_wait0()  { asm volatile("cp.async.wait_group 0;"); }

// ---------------------------------------------------------------------------
// Kernel 0: x -> bf16 (g_xb). 8 elems/thread.
// ---------------------------------------------------------------------------
__global__ void xcvt_kernel(const float* __restrict__ x)
{
    size_t i8 = ((size_t)blockIdx.x * 256 + threadIdx.x) * 8;
    float4 a = *(const float4*)(x + i8);
    float4 c = *(const float4*)(x + i8 + 4);
    __nv_bfloat162 o[4];
    o[0] = __floats2bfloat162_rn(a.x, a.y);
    o[1] = __floats2bfloat162_rn(a.z, a.w);
    o[2] = __floats2bfloat162_rn(c.x, c.y);
    o[3] = __floats2bfloat162_rn(c.z, c.w);
    *(uint4*)(g_xb + i8) = *(uint4*)o;
}

// ---------------------------------------------------------------------------
// Kernel 1: unified projection GEMM (unchanged — verified correct R13).
// ---------------------------------------------------------------------------
#define P2_LDW 264
#define P2_LDX 136
#define P2_W_ELEMS (64 * P2_LDW)
#define P2_X_STG   (32 * P2_LDX)
#define P2_SMEM_BYTES ((P2_W_ELEMS + 2 * P2_X_STG) * 2 + 64 * 4)

__global__ __launch_bounds__(256) void proj2_kernel(
    const float* __restrict__ Wf, const float* __restrict__ bfp,
    const float* __restrict__ Wg, const float* __restrict__ bgp,
    const float* __restrict__ Wh, const float* __restrict__ bhp)
{
    extern __shared__ __nv_bfloat16 sm[];
    __nv_bfloat16* Wt = sm;                        // [64][264]
    __nv_bfloat16* xs = Wt + P2_W_ELEMS;           // [2][32][136]
    float* bias_s = (float*)(xs + 2 * P2_X_STG);   // [64]

    const int b   = blockIdx.z;
    const int y   = blockIdx.y;
    const int n0  = blockIdx.x * 128;
    const int tid = threadIdx.x;
    const int w   = tid >> 5;
    const int l   = tid & 31;
    const int rw  = (w >> 1);
    const int cg  = (w & 1);

    for (int idx = tid; idx < 64 * 256; idx += 256) {
        int r = idx >> 8, c = idx & 255;
        float v;
        if (y == 0) v = (r < 32) ? Wf[r * CC + c] : Wg[(r - 32) * CC + c];
        else        v = Wh[((size_t)((y - 1) * 64 + r)) * CC + c];
        Wt[r * P2_LDW + c] = __float2bfloat16(v);
    }
    if (tid < 64) {
        float bv;
        if (y == 0) bv = (tid < 32) ? bfp[tid] : bgp[tid - 32];
        else        bv = bhp[(y - 1) * 64 + tid];
        bias_s[tid] = bv;
    }

    const __nv_bfloat16* xbb = g_xb + (size_t)b * CC * NN;

    auto issue_x = [&](int kt, int s) {
        int k0 = kt * 32;
#pragma unroll
        for (int p = 0; p < 2; p++) {
            int id = tid + p * 256;
            int r = id >> 4, q = id & 15;
            cp_async16(smem_u32(xs + s * P2_X_STG + r * P2_LDX + q * 8),
                       xbb + (size_t)(k0 + r) * NN + n0 + q * 8);
        }
    };

    issue_x(0, 0); cp_commit();
    issue_x(1, 1); cp_commit();

    float acc[8][4];
#pragma unroll
    for (int n8 = 0; n8 < 8; n8++)
#pragma unroll
        for (int e = 0; e < 4; e++) acc[n8][e] = 0.0f;

    const int NIT = CC / 32;   // 8
    for (int it = 0; it < NIT; it++) {
        if (it < NIT - 1) cp_wait1(); else cp_wait0();
        __syncthreads();
        const int s = it & 1;
#pragma unroll
        for (int kd = 0; kd < 2; kd++) {
            uint32_t aW[4];
            ldsm_x4(aW[0], aW[1], aW[2], aW[3],
                    smem_u32(Wt + (rw * 16 + (l & 15)) * P2_LDW +
                             it * 32 + kd * 16 + (l >> 4) * 8));
#pragma unroll
            for (int n8 = 0; n8 < 8; n8++) {
                uint32_t b0, b1;
                ldsm_x2_t(b0, b1, smem_u32(xs + s * P2_X_STG +
                                           (kd * 16 + (l & 15)) * P2_LDX +
                                           cg * 64 + n8 * 8));
                mma_16816(acc[n8], aW, b0, b1);
            }
        }
        __syncthreads();
        if (it + 2 < NIT) { issue_x(it + 2, s); cp_commit(); }
        else              { cp_commit(); }
    }

#pragma unroll
    for (int n8 = 0; n8 < 8; n8++) {
        int ml0 = rw * 16 + (l >> 2);
        int col = n0 + cg * 64 + n8 * 8 + (l & 3) * 2;
#pragma unroll
        for (int half = 0; half < 2; half++) {
            int ml = ml0 + half * 8;
            float v0 = acc[n8][half * 2 + 0] + bias_s[ml];
            float v1 = acc[n8][half * 2 + 1] + bias_s[ml];
            if (y == 0) {
                if (ml < 32) {
                    *(__nv_bfloat162*)(g_fK + ((size_t)b * DKK + ml) * NN + col) =
                        __floats2bfloat162_rn(v0, v1);
                } else {
                    int d = ml - 32;
                    g_gT[((size_t)b * NN + col)     * DKK + d] = __float2bfloat16(v0);
                    g_gT[((size_t)b * NN + col + 1) * DKK + d] = __float2bfloat16(v1);
                }
            } else {
                int hr = (y - 1) * 64 + ml;
                *(__nv_bfloat162*)(g_hc + ((size_t)b * CC + hr) * NN + col) =
                    __floats2bfloat162_rn(v0, v1);
            }
        }
    }
}

// ---------------------------------------------------------------------------
// Kernel 2: reciprocal row sums (unchanged — verified correct R13).
// ---------------------------------------------------------------------------
__global__ __launch_bounds__(256) void z_kernel()
{
    __shared__ __nv_bfloat16 Ags[64][40];
    __shared__ __nv_bfloat16 Bfs[2][32][72];
    __shared__ float         Zp[2][64];

    const int b   = blockIdx.y;
    const int j0  = blockIdx.x * 64;
    const int tid = threadIdx.x;
    const int w   = tid >> 5;
    const int l   = tid & 31;
    const int jr  = (w >> 1) * 16;
    const int cw  = (w & 1);

    {
        int r = tid >> 2, q = tid & 3;
        *(uint4*)&Ags[r][q * 8] =
            *(const uint4*)(g_gT + ((size_t)b * NN + j0 + r) * DKK + q * 8);
    }
    {
        int r = tid >> 3, q = tid & 7;
        *(uint4*)&Bfs[0][r][q * 8] =
            *(const uint4*)(g_fK + ((size_t)b * DKK + r) * NN + q * 8);
    }
    __syncthreads();

    uint32_t a[2][4];
#pragma unroll
    for (int kf = 0; kf < 2; kf++) {
        uint32_t addr = smem_u32(&Ags[jr + (l & 15)][kf * 16 + (l >> 4) * 8]);
        ldsm_x4(a[kf][0], a[kf][1], a[kf][2], a[kf][3], addr);
    }

    float zacc0 = 0.0f, zacc1 = 0.0f;

    const int NIT = NN / 64;
    for (int it = 0; it < NIT; it++) {
        const int cur = it & 1;
        uint4 rnext;
        if (it + 1 < NIT) {
            int r = tid >> 3, q = tid & 7;
            rnext = *(const uint4*)(g_fK + ((size_t)b * DKK + r) * NN +
                                    (it + 1) * 64 + q * 8);
        }
#pragma unroll
        for (int nf = 0; nf < 4; nf++) {
            const int cb = cw * 32 + nf * 8;
            float d[4] = {0.f, 0.f, 0.f, 0.f};
            uint32_t b0, b1;
            ldsm_x2_t(b0, b1, smem_u32(&Bfs[cur][l & 15][cb]));
            mma_16816(d, a[0], b0, b1);
            ldsm_x2_t(b0, b1, smem_u32(&Bfs[cur][16 + (l & 15)][cb]));
            mma_16816(d, a[1], b0, b1);
            zacc0 += __expf(d[0]) + __expf(d[1]);
            zacc1 += __expf(d[2]) + __expf(d[3]);
        }
        if (it + 1 < NIT) {
            int r = tid >> 3, q = tid & 7;
            *(uint4*)&Bfs[cur ^ 1][r][q * 8] = rnext;
        }
        __syncthreads();
    }

    zacc0 += __shfl_xor_sync(0xFFFFFFFFu, zacc0, 1);
    zacc0 += __shfl_xor_sync(0xFFFFFFFFu, zacc0, 2);
    zacc1 += __shfl_xor_sync(0xFFFFFFFFu, zacc1, 1);
    zacc1 += __shfl_xor_sync(0xFFFFFFFFu, zacc1, 2);
    if ((l & 3) == 0) {
        int r1 = jr + (l >> 2);
        Zp[cw][r1]     = zacc0;
        Zp[cw][r1 + 8] = zacc1;
    }
    __syncthreads();
    if (tid < 64)
        g_Z[(size_t)b * NN + j0 + tid] = 1.0f / (Zp[0][tid] + Zp[1][tid]);
}

// ---------------------------------------------------------------------------
// Kernel 3 (fused, skewed single-barrier): per CTA = full 256 c-rows x 128 i.
// 512 threads, 128 CTAs (single wave, 1 CTA/SM).
// Iteration: oGEMM(it) [reads E_s[it&1], hc(it%3)] -> E-compute(it+1)
// [writes E_s[(it+1)&1], reads gT((it+1)%3)] -> prefetch -> wait -> ONE sync.
// cp.async group G_k = { hc(k), gT(k+1) }.
// ---------------------------------------------------------------------------
#define FO_LDF 136
#define FO_LDG 40
#define FO_LDE 136
#define FO_LDH 72
#define FO_F_ELEMS   (32 * FO_LDF)
#define FO_G_STG     (64 * FO_LDG)
#define FO_E_STG     (64 * FO_LDE)
#define FO_H_STG     (256 * FO_LDH)
#define FO_SMEM_ELEMS (FO_F_ELEMS + 3 * FO_G_STG + 2 * FO_E_STG + 3 * FO_H_STG)
#define FO_SMEM_BYTES (FO_SMEM_ELEMS * 2)   // 169472 bytes

__global__ __launch_bounds__(512, 1) void fused_out_kernel(const float* __restrict__ x,
                                                           float* __restrict__ out)
{
    extern __shared__ __nv_bfloat16 smf[];
    __nv_bfloat16* f_s  = smf;                         // [32][136]
    __nv_bfloat16* gT_s = f_s + FO_F_ELEMS;            // [3][64][40]
    __nv_bfloat16* E_s  = gT_s + 3 * FO_G_STG;         // [2][64][136]
    __nv_bfloat16* hc_s = E_s + 2 * FO_E_STG;          // [3][256][72]

    const int b   = blockIdx.y;
    const int i0  = blockIdx.x * 128;
    const int tid = threadIdx.x;
    const int w   = tid >> 5;
    const int l   = tid & 31;

    const int re = (w & 3) * 16;    // E rows
    const int ce = (w >> 2);        // E col group (*32)
    const int rw = (w >> 1);        // o row group (*32)
    const int cg = (w & 1);         // o col group (*64)

    const __nv_bfloat16* fKb = g_fK + (size_t)b * DKK * NN;
    const __nv_bfloat16* gTb = g_gT + (size_t)b * NN * DKK;
    const __nv_bfloat16* hcb = g_hc + (size_t)b * CC * NN;
    const float*         rZb = g_Z  + (size_t)b * NN;

    const int NIT = NN / 64;   // 64

    // ---- f tile [32][128] (plain stores, one uint4 per thread) ----
    {
        int r = tid >> 4, q = tid & 15;
        *(uint4*)(f_s + r * FO_LDF + q * 8) =
            *(const uint4*)(fKb + (size_t)r * NN + i0 + q * 8);
    }

    // gT loader: tile jt -> gT_s[jt%3]
    auto issue_gT = [&](int jt) {
        if (jt < NIT && tid < 256) {
            int r = tid >> 2, q = tid & 3;
            cp_async16(smem_u32(gT_s + (jt % 3) * FO_G_STG + r * FO_LDG + q * 8),
                       gTb + (size_t)((size_t)jt * 64 + r) * DKK + q * 8);
        }
    };
    // group G_k = { hc(k), gT(k+1) }
    auto issue_group = [&](int k) {
        if (k < NIT) {
            int j0s = k * 64;
#pragma unroll
            for (int p = 0; p < 4; p++) {
                int id = tid + p * 512;
                int r = id >> 3, q = id & 7;
                cp_async16(smem_u32(hc_s + (k % 3) * FO_H_STG + r * FO_LDH + q * 8),
                           hcb + (size_t)r * NN + j0s + q * 8);
            }
        }
        issue_gT(k + 1);
    };

    issue_gT(0);     cp_commit();   // G_a
    issue_group(0);  cp_commit();   // G_0 = hc0 + gT1
    issue_group(1);  cp_commit();   // G_1 = hc1 + gT2

    cp_wait1();          // G_a, G_0 complete (G_1 in flight)
    __syncthreads();     // f_s, gT0, hc0, gT1 visible to all

    // ---- preload f B-fragments (register-resident for whole kernel) ----
    uint32_t bf_f[2][4][2];
#pragma unroll
    for (int kd = 0; kd < 2; kd++)
#pragma unroll
        for (int nf = 0; nf < 4; nf++)
            ldsm_x2_t(bf_f[kd][nf][0], bf_f[kd][nf][1],
                      smem_u32(f_s + (kd * 16 + (l & 15)) * FO_LDF + ce * 32 + nf * 8));

    // ---- E-compute for tile jt into buffer dst ----
    auto e_compute = [&](int jt, __nv_bfloat16* dst) {
        const int j0s = jt * 64;
        const int r1  = re + (l >> 2);
        const float rzA = __ldg(rZb + j0s + r1);
        const float rzB = __ldg(rZb + j0s + r1 + 8);
        uint32_t aG[2][4];
#pragma unroll
        for (int kd = 0; kd < 2; kd++)
            ldsm_x4(aG[kd][0], aG[kd][1], aG[kd][2], aG[kd][3],
                    smem_u32(gT_s + (jt % 3) * FO_G_STG + (re + (l & 15)) * FO_LDG +
                             kd * 16 + (l >> 4) * 8));
#pragma unroll
        for (int nf = 0; nf < 4; nf++) {
            float d[4] = {0.f, 0.f, 0.f, 0.f};
            mma_16816(d, aG[0], bf_f[0][nf][0], bf_f[0][nf][1]);
            mma_16816(d, aG[1], bf_f[1][nf][0], bf_f[1][nf][1]);
            float e0 = __expf(d[0]) * rzA, e1 = __expf(d[1]) * rzA;
            float e2 = __expf(d[2]) * rzB, e3 = __expf(d[3]) * rzB;
            int col = ce * 32 + nf * 8 + (l & 3) * 2;
            *(__nv_bfloat162*)(dst + (size_t)r1 * FO_LDE + col)       = __floats2bfloat162_rn(e0, e1);
            *(__nv_bfloat162*)(dst + (size_t)(r1 + 8) * FO_LDE + col) = __floats2bfloat162_rn(e2, e3);
        }
    };

    e_compute(0, E_s);       // E_s[0]
    __syncthreads();         // E_s[0] visible

    float acc[2][8][4];
#pragma unroll
    for (int mi = 0; mi < 2; mi++)
#pragma unroll
        for (int n8 = 0; n8 < 8; n8++)
#pragma unroll
            for (int e = 0; e < 4; e++) acc[mi][n8][e] = 0.0f;

    for (int it = 0; it < NIT; it++) {
        // ---- 1. o-GEMM: acc += hc(it) @ E_s[it&1] ----
        const __nv_bfloat16* Ebuf = E_s + (it & 1) * FO_E_STG;
        const __nv_bfloat16* hcs  = hc_s + (it % 3) * FO_H_STG;
#pragma unroll
        for (int kk = 0; kk < 4; kk++) {
            uint32_t aH[2][4];
#pragma unroll
            for (int mi = 0; mi < 2; mi++)
                ldsm_x4(aH[mi][0], aH[mi][1], aH[mi][2], aH[mi][3],
                        smem_u32(hcs + (rw * 32 + mi * 16 + (l & 15)) * FO_LDH +
                                 kk * 16 + (l >> 4) * 8));
#pragma unroll
            for (int n8 = 0; n8 < 8; n8++) {
                uint32_t b0, b1;
                ldsm_x2_t(b0, b1, smem_u32(Ebuf + (size_t)(kk * 16 + (l & 15)) * FO_LDE +
                                           cg * 64 + n8 * 8));
                mma_16816(acc[0][n8], aH[0], b0, b1);
                mma_16816(acc[1][n8], aH[1], b0, b1);
            }
        }

        // ---- 2. E-compute(it+1) into the other buffer (no sync needed) ----
        if (it + 1 < NIT)
            e_compute(it + 1, E_s + ((it + 1) & 1) * FO_E_STG);

        // ---- 3. prefetch G_{it+2}; 4. wait; 5. single barrier ----
        issue_group(it + 2);
        cp_commit();
        if (it < NIT - 1) cp_wait1(); else cp_wait0();
        __syncthreads();
    }

    // ---- epilogue: out = acc + x ----
    const float* xb = x   + (size_t)b * CC * NN;
    float*       ob = out + (size_t)b * CC * NN;
#pragma unroll
    for (int mi = 0; mi < 2; mi++) {
#pragma unroll
        for (int n8 = 0; n8 < 8; n8++) {
            int row0 = rw * 32 + mi * 16 + (l >> 2);
            int col  = i0 + cg * 64 + n8 * 8 + (l & 3) * 2;
            float2 xv0 = *(const float2*)(xb + (size_t)row0 * NN + col);
            *(float2*)(ob + (size_t)row0 * NN + col) =
                make_float2(acc[mi][n8][0] + xv0.x, acc[mi][n8][1] + xv0.y);
            float2 xv1 = *(const float2*)(xb + (size_t)(row0 + 8) * NN + col);
            *(float2*)(ob + (size_t)(row0 + 8) * NN + col) =
                make_float2(acc[mi][n8][2] + xv1.x, acc[mi][n8][3] + xv1.y);
        }
    }
}

// ---------------------------------------------------------------------------
// Launch
// ---------------------------------------------------------------------------
extern "C" void kernel_launch(void* const* d_in, const int* in_sizes, int n_in,
                              void* d_out, int out_size)
{
    const float* x  = (const float*)d_in[0];
    const float* Wf = (const float*)d_in[1];
    const float* bf = (const float*)d_in[2];
    const float* Wg = (const float*)d_in[3];
    const float* bg = (const float*)d_in[4];
    const float* Wh = (const float*)d_in[5];
    const float* bh = (const float*)d_in[6];
    float* out = (float*)d_out;

    cudaFuncSetAttribute(proj2_kernel,
                         cudaFuncAttributeMaxDynamicSharedMemorySize, P2_SMEM_BYTES);
    cudaFuncSetAttribute(fused_out_kernel,
                         cudaFuncAttributeMaxDynamicSharedMemorySize, FO_SMEM_BYTES);

    xcvt_kernel<<<(BATCH * CC * NN) / (256 * 8), 256>>>(x);

    dim3 gP(NN / 128, 5, BATCH);
    proj2_kernel<<<gP, 256, P2_SMEM_BYTES>>>(Wf, bf, Wg, bg, Wh, bh);

    dim3 gZ(NN / 64, BATCH);
    z_kernel<<<gZ, 256>>>();

    dim3 gO(NN / 128, BATCH);
    fused_out_kernel<<<gO, 512, FO_SMEM_BYTES>>>(x, out);
}